// round 1
// baseline (speedup 1.0000x reference)
#include <cuda_runtime.h>
#include <cuda_bf16.h>
#include <math.h>

// ContrastiveLoss: x (8192,256) fp32 -> scalar fp32 loss.
// Decomposition: loss = log(S_A_upper + S_C_upper + S_B_full + sim_s) - log(sim_s)
//   A = U U^T (p-normalized), C = V V^T (q-normalized), B = U V^T,
//   sim_s = sum_i exp(B_ii / 2).
// All GEMM tiles fused with exp + reduction; nothing 4096x4096 is materialized.

#define NROWS 8192
#define NHALF 4096
#define D     256
#define NT    32          // 4096 / 128 tiles per dim
#define NUPPER 528        // NT*(NT+1)/2
#define NFULL 1024        // NT*NT

__device__ float  g_xn[NROWS * D];   // normalized rows (8 MB, static -> allocation-free)
__device__ double g_main;            // S_A_upper + S_C_upper + S_B_full
__device__ double g_sims;            // sim_s

// ---------------------------------------------------------------------------
__global__ void init_k() {
    g_main = 0.0;
    g_sims = 0.0;
}

// One block per row: normalize by L2 norm (clamped).
__global__ __launch_bounds__(256) void normalize_k(const float* __restrict__ x) {
    const int row = blockIdx.x;
    const int t   = threadIdx.x;
    float v = x[row * D + t];
    __shared__ float red[256];
    red[t] = v * v;
    __syncthreads();
    #pragma unroll
    for (int s = 128; s > 0; s >>= 1) {
        if (t < s) red[t] += red[t + s];
        __syncthreads();
    }
    float norm = sqrtf(red[0]);
    float inv  = 1.0f / fmaxf(norm, 1e-8f);
    g_xn[row * D + t] = v * inv;
}

// diag(B)_i = dot(U_i, V_i); accumulate exp(./2) into g_sims.
__global__ __launch_bounds__(256) void diag_k() {
    const int row = blockIdx.x;          // 0..4095
    const int t   = threadIdx.x;
    float a = g_xn[row * D + t];
    float b = g_xn[(NHALF + row) * D + t];
    __shared__ float red[256];
    red[t] = a * b;
    __syncthreads();
    #pragma unroll
    for (int s = 128; s > 0; s >>= 1) {
        if (t < s) red[t] += red[t + s];
        __syncthreads();
    }
    if (t == 0) atomicAdd(&g_sims, (double)__expf(0.5f * red[0]));
}

// ---------------------------------------------------------------------------
// Fused tile GEMM: 128x128 output tile, K=256, exp + weighted sum epilogue.
// Block schedule:
//   blocks [0, 1024):         B = U V^T   (full matrix, weight 1)
//   blocks [1024, 1024+528):  A = U U^T   upper-tri tiles (bi<=bj)
//   blocks [1552, 2080):      C = V V^T   upper-tri tiles (bi<=bj)
// For diagonal tiles of A/C only elements with gcol >= grow are counted.
__global__ __launch_bounds__(256) void tile_k() {
    int t = blockIdx.x;
    int bi, bj;
    const float* Ap;
    const float* Bp;
    bool symdiag = false;

    if (t < NFULL) {
        bi = t >> 5;
        bj = t & 31;
        Ap = g_xn;                 // p rows
        Bp = g_xn + NHALF * D;     // q rows
    } else {
        t -= NFULL;
        int m = (t >= NUPPER) ? 1 : 0;
        int u = t - m * NUPPER;
        int bi_ = 0;
        while (u >= NT - bi_) { u -= NT - bi_; bi_++; }
        bi = bi_;
        bj = bi_ + u;
        const float* base = g_xn + m * NHALF * D;
        Ap = base;
        Bp = base;
        symdiag = (bi == bj);
    }

    __shared__ float As[16][128];
    __shared__ float Bs[16][128];

    const int tx = threadIdx.x & 15;   // output col group
    const int ty = threadIdx.x >> 4;   // output row group

    float acc[8][8];
    #pragma unroll
    for (int i = 0; i < 8; i++)
        #pragma unroll
        for (int j = 0; j < 8; j++) acc[i][j] = 0.0f;

    const int rowA = bi * 128;
    const int rowB = bj * 128;

    for (int kk = 0; kk < D; kk += 16) {
        // Load 128x16 of each operand (transpose into k-major smem).
        #pragma unroll
        for (int i = 0; i < 2; i++) {
            int id = threadIdx.x + i * 256;  // 0..511
            int r  = id >> 2;                // row in tile
            int q  = id & 3;                 // float4 index in k-chunk
            float4 va = *(const float4*)&Ap[(rowA + r) * D + kk + q * 4];
            As[q * 4 + 0][r] = va.x;
            As[q * 4 + 1][r] = va.y;
            As[q * 4 + 2][r] = va.z;
            As[q * 4 + 3][r] = va.w;
            float4 vb = *(const float4*)&Bp[(rowB + r) * D + kk + q * 4];
            Bs[q * 4 + 0][r] = vb.x;
            Bs[q * 4 + 1][r] = vb.y;
            Bs[q * 4 + 2][r] = vb.z;
            Bs[q * 4 + 3][r] = vb.w;
        }
        __syncthreads();

        #pragma unroll
        for (int k = 0; k < 16; k++) {
            float a[8], b[8];
            *(float4*)&a[0] = *(const float4*)&As[k][ty * 8 + 0];
            *(float4*)&a[4] = *(const float4*)&As[k][ty * 8 + 4];
            *(float4*)&b[0] = *(const float4*)&Bs[k][tx * 8 + 0];
            *(float4*)&b[4] = *(const float4*)&Bs[k][tx * 8 + 4];
            #pragma unroll
            for (int i = 0; i < 8; i++)
                #pragma unroll
                for (int j = 0; j < 8; j++)
                    acc[i][j] = fmaf(a[i], b[j], acc[i][j]);
        }
        __syncthreads();
    }

    // Epilogue: exp(s/2), triangular weighting on diagonal tiles, reduce.
    float s = 0.0f;
    #pragma unroll
    for (int i = 0; i < 8; i++) {
        #pragma unroll
        for (int j = 0; j < 8; j++) {
            float e = __expf(0.5f * acc[i][j]);
            if (symdiag) {
                int gi = ty * 8 + i;      // local row within tile
                int gj = tx * 8 + j;      // local col within tile
                if (gj < gi) e = 0.0f;
            }
            s += e;
        }
    }

    __shared__ float red[256];
    red[threadIdx.x] = s;
    __syncthreads();
    #pragma unroll
    for (int st = 128; st > 0; st >>= 1) {
        if (threadIdx.x < st) red[threadIdx.x] += red[threadIdx.x + st];
        __syncthreads();
    }
    if (threadIdx.x == 0) atomicAdd(&g_main, (double)red[0]);
}

// ---------------------------------------------------------------------------
__global__ void fin_k(float* __restrict__ out) {
    double sim_all = g_main + g_sims;
    out[0] = (float)(log(sim_all) - log(g_sims));
}

extern "C" void kernel_launch(void* const* d_in, const int* in_sizes, int n_in,
                              void* d_out, int out_size) {
    const float* x = (const float*)d_in[0];
    float* out = (float*)d_out;

    init_k<<<1, 1>>>();
    normalize_k<<<NROWS, 256>>>(x);
    diag_k<<<NHALF, 256>>>();
    tile_k<<<NFULL + 2 * NUPPER, 256>>>();
    fin_k<<<1, 1>>>(out);
}

// round 3
// speedup vs baseline: 3.9030x; 3.9030x over previous
#include <cuda_runtime.h>
#include <cuda_bf16.h>
#include <math.h>
#include <stdint.h>

// ContrastiveLoss via warp-level bf16 mma.sync (HMMA) — no tcgen05 (ptxas
// targets plain sm_103 which rejects tcgen05; mma.sync is baseline PTX).
//
// loss = log(S_A_up + S_C_up + S_B_full + sim_s) - log(sim_s)
//   A = U U^T, C = V V^T, B = U V^T  (U,V = L2-normalized halves of x)
//   sim_s = sum_i exp(diag(B)_i / 2)  in exact fp32.
//
// g_xb: 64 bands of 128 rows; band = 4 K-blocks; K-block = 128 rows x 64 K
// bf16 = 128 rows x 128B, SW128-swizzled, 16KB contiguous -> cp.async.bulk.

#define D      256
#define NROWS  8192
#define NHALF  4096
#define NT     32
#define BAND_BYTES 65536
#define KBLK_BYTES 16384
#define STAGE_BYTES 32768              // A 16KB + B 16KB
#define SMEM_DATA   1024
#define SMEM_TOTAL  (SMEM_DATA + 2 * STAGE_BYTES)   // 66560

#define MB_FULL0  16
#define MB_FULL1  24
#define MB_EMPTY0 32
#define MB_EMPTY1 40

__device__ __align__(128) uint8_t g_xb[NROWS * D * 2];   // 4 MB bf16 swizzled
__device__ float  g_inv[NROWS];
__device__ double g_main;
__device__ double g_sims;

// ---------------------------------------------------------------------------
static __device__ __forceinline__ uint32_t smem_u32(const void* p) {
    uint32_t a;
    asm("{ .reg .u64 t; cvta.to.shared.u64 t, %1; cvt.u32.u64 %0, t; }"
        : "=r"(a) : "l"(p));
    return a;
}

#define MBAR_INIT(addr, cnt) \
    asm volatile("mbarrier.init.shared.b64 [%0], %1;" :: "r"(addr), "r"(cnt) : "memory")

#define MBAR_ARRIVE(addr) \
    asm volatile("mbarrier.arrive.shared.b64 _, [%0];" :: "r"(addr) : "memory")

#define MBAR_EXPECT_TX(addr, bytes) \
    asm volatile("mbarrier.arrive.expect_tx.shared.b64 _, [%0], %1;" \
                 :: "r"(addr), "r"(bytes) : "memory")

#define MBAR_WAIT(addr, parity) do {                                          \
    uint32_t _m = (addr); uint32_t _p = (parity); uint32_t _done;             \
    asm volatile("{\n\t.reg .pred p;\n\t"                                     \
        "mbarrier.try_wait.parity.acquire.cta.shared::cta.b64 p, [%1], %2;\n\t"\
        "selp.b32 %0, 1, 0, p;\n\t}"                                          \
        : "=r"(_done) : "r"(_m), "r"(_p) : "memory");                         \
    if (!_done) {                                                             \
        asm volatile("{\n\t.reg .pred P1;\n\t"                                \
            "W_%=:\n\t"                                                       \
            "mbarrier.try_wait.parity.acquire.cta.shared::cta.b64 P1, [%0], %1, 0x989680;\n\t" \
            "@P1 bra.uni WD_%=;\n\t"                                          \
            "bra.uni W_%=;\n\t"                                               \
            "WD_%=:\n\t}" :: "r"(_m), "r"(_p) : "memory");                    \
    }                                                                         \
} while (0)

#define BULK_G2S(dst, src, bytes, mbar) \
    asm volatile("cp.async.bulk.shared::cta.global.mbarrier::complete_tx::bytes [%0], [%1], %2, [%3];" \
                 :: "r"(dst), "l"(src), "r"(bytes), "r"(mbar) : "memory")

static __device__ __forceinline__ void ldsm_x4(uint32_t* r, uint32_t addr) {
    asm volatile("ldmatrix.sync.aligned.m8n8.x4.shared.b16 {%0,%1,%2,%3}, [%4];"
                 : "=r"(r[0]), "=r"(r[1]), "=r"(r[2]), "=r"(r[3]) : "r"(addr));
}

static __device__ __forceinline__ void mma16816(float* d, const uint32_t* a,
                                                uint32_t b0, uint32_t b1) {
    asm volatile("mma.sync.aligned.m16n8k16.row.col.f32.bf16.bf16.f32 "
                 "{%0,%1,%2,%3}, {%4,%5,%6,%7}, {%8,%9}, {%0,%1,%2,%3};"
                 : "+f"(d[0]), "+f"(d[1]), "+f"(d[2]), "+f"(d[3])
                 : "r"(a[0]), "r"(a[1]), "r"(a[2]), "r"(a[3]), "r"(b0), "r"(b1));
}

static __device__ __forceinline__ uint32_t sw128(uint32_t off) {
    return off ^ ((off >> 3) & 0x70);
}

// ---------------------------------------------------------------------------
__global__ void init_k() { g_main = 0.0; g_sims = 0.0; }

__global__ __launch_bounds__(256) void normalize_k(const float* __restrict__ x) {
    const int row = blockIdx.x;
    const int t   = threadIdx.x;
    float v = x[row * D + t];
    __shared__ float red[256];
    red[t] = v * v;
    __syncthreads();
    #pragma unroll
    for (int s = 128; s > 0; s >>= 1) {
        if (t < s) red[t] += red[t + s];
        __syncthreads();
    }
    float inv = 1.0f / fmaxf(sqrtf(red[0]), 1e-8f);
    if (t == 0) g_inv[row] = inv;

    int band = row >> 7, rib = row & 127;
    int kb = t >> 6, kw = t & 63;
    uint32_t off = sw128((uint32_t)(rib * 128 + kw * 2));
    *reinterpret_cast<__nv_bfloat16*>(g_xb + (size_t)band * BAND_BYTES
                                      + (size_t)kb * KBLK_BYTES + off)
        = __float2bfloat16(v * inv);
}

__global__ __launch_bounds__(256) void diag_k(const float* __restrict__ x) {
    const int row = blockIdx.x;
    const int t   = threadIdx.x;
    float a = x[row * D + t];
    float b = x[(NHALF + row) * D + t];
    __shared__ float red[256];
    red[t] = a * b;
    __syncthreads();
    #pragma unroll
    for (int s = 128; s > 0; s >>= 1) {
        if (t < s) red[t] += red[t + s];
        __syncthreads();
    }
    if (t == 0) {
        float c = red[0] * g_inv[row] * g_inv[NHALF + row];
        atomicAdd(&g_sims, (double)__expf(0.5f * c));
    }
}

// ---------------------------------------------------------------------------
// One CTA = one 128x128x256 tile. 1024 B-full + 528 A-upper + 528 C-upper.
__global__ __launch_bounds__(256, 2) void tile_k() {
    extern __shared__ __align__(1024) uint8_t smem[];
    uint32_t sb = smem_u32(smem);
    const int tid  = threadIdx.x;
    const int wid  = tid >> 5;
    const int lane = tid & 31;

    // ---- tile decode ----
    int t = blockIdx.x;
    int bi, bj;
    bool maskt = false;
    const uint8_t *gA, *gB;
    if (t < 1024) {                       // B = U V^T, full
        bi = t >> 5; bj = t & 31;
        gA = g_xb + (size_t)bi * BAND_BYTES;
        gB = g_xb + (size_t)(32 + bj) * BAND_BYTES;
    } else {                              // A (m=0) / C (m=1), upper
        t -= 1024;
        int m = (t >= 528) ? 1 : 0;
        int u = t - m * 528;
        int b_ = 0;
        while (u >= NT - b_) { u -= NT - b_; b_++; }
        bi = b_; bj = b_ + u;
        maskt = (bi == bj);
        gA = g_xb + (size_t)(m * 32 + bi) * BAND_BYTES;
        gB = g_xb + (size_t)(m * 32 + bj) * BAND_BYTES;
    }

    if (tid == 0) {
        MBAR_INIT(sb + MB_FULL0, 1);  MBAR_INIT(sb + MB_FULL1, 1);
        MBAR_INIT(sb + MB_EMPTY0, 8); MBAR_INIT(sb + MB_EMPTY1, 8);
    }
    __syncthreads();

    if (tid == 0) {
        #pragma unroll
        for (int s = 0; s < 2; s++) {
            uint32_t stb = sb + SMEM_DATA + s * STAGE_BYTES;
            uint32_t fb  = sb + MB_FULL0 + 8 * s;
            MBAR_EXPECT_TX(fb, (uint32_t)STAGE_BYTES);
            BULK_G2S(stb,         gA + s * KBLK_BYTES, KBLK_BYTES, fb);
            BULK_G2S(stb + 16384, gB + s * KBLK_BYTES, KBLK_BYTES, fb);
        }
    }

    // ---- per-warp geometry ----
    const int warp_m = wid & 3;        // 32-row strip
    const int warp_n = wid >> 2;       // 64-col strip
    // ldmatrix lane roles (same for A and B strips):
    const int lrow = lane & 15;                 // row within 16-row group
    const uint32_t xoff = ((lane >> 4) & 1) * 16;  // second 8-col half

    float d[2][8][4];
    #pragma unroll
    for (int i = 0; i < 2; i++)
        #pragma unroll
        for (int j = 0; j < 8; j++)
            #pragma unroll
            for (int k = 0; k < 4; k++) d[i][j][k] = 0.0f;

    // Precompute per-lane swizzled row offsets (coloff < 128 doesn't affect XOR)
    uint32_t aRow[2], bRow[4];
    #pragma unroll
    for (int am = 0; am < 2; am++) {
        int r = warp_m * 32 + am * 16 + lrow;
        aRow[am] = (uint32_t)(r * 128) + (uint32_t)((r & 7) << 4);  // row ^ pre-applied? no:
    }
    // NOTE: sw128(rowoff + coloff) = rowoff + (coloff ^ ((row&7)<<4)); store both parts
    uint32_t aSw[2], bSw[4];
    #pragma unroll
    for (int am = 0; am < 2; am++) {
        int r = warp_m * 32 + am * 16 + lrow;
        aRow[am] = (uint32_t)(r * 128);
        aSw[am]  = (uint32_t)((r & 7) << 4);
    }
    #pragma unroll
    for (int bg = 0; bg < 4; bg++) {
        int r = warp_n * 64 + bg * 16 + lrow;
        bRow[bg] = (uint32_t)(r * 128);
        bSw[bg]  = (uint32_t)((r & 7) << 4);
    }

    // ---- chunk loop: 4 chunks of K=64 ----
    #pragma unroll
    for (int c = 0; c < 4; c++) {
        const int st = c & 1;
        const uint32_t stA = sb + SMEM_DATA + st * STAGE_BYTES;
        const uint32_t stB = stA + 16384;
        MBAR_WAIT(sb + MB_FULL0 + 8 * st, (uint32_t)((c >> 1) & 1));

        #pragma unroll
        for (int ks = 0; ks < 4; ks++) {
            const uint32_t kc = (uint32_t)(ks * 32);
            uint32_t a[2][4], b[4][4];
            #pragma unroll
            for (int am = 0; am < 2; am++)
                ldsm_x4(a[am], stA + aRow[am] + ((kc + xoff) ^ aSw[am]));
            #pragma unroll
            for (int bg = 0; bg < 4; bg++)
                ldsm_x4(b[bg], stB + bRow[bg] + ((kc + xoff) ^ bSw[bg]));

            #pragma unroll
            for (int am = 0; am < 2; am++)
                #pragma unroll
                for (int bg = 0; bg < 4; bg++) {
                    mma16816(d[am][bg * 2 + 0], a[am], b[bg][0], b[bg][2]);
                    mma16816(d[am][bg * 2 + 1], a[am], b[bg][1], b[bg][3]);
                }
        }

        if (lane == 0) MBAR_ARRIVE(sb + MB_EMPTY0 + 8 * st);
        if (tid == 0 && c < 2) {
            MBAR_WAIT(sb + MB_EMPTY0 + 8 * st, 0u);
            uint32_t fb = sb + MB_FULL0 + 8 * st;
            MBAR_EXPECT_TX(fb, (uint32_t)STAGE_BYTES);
            BULK_G2S(stA, gA + (c + 2) * KBLK_BYTES, KBLK_BYTES, fb);
            BULK_G2S(stB, gB + (c + 2) * KBLK_BYTES, KBLK_BYTES, fb);
        }
    }

    // ---- epilogue: exp + triangular mask + reduce ----
    const int rbase = warp_m * 32 + (lane >> 2);
    const int cbase = warp_n * 64 + 2 * (lane & 3);
    float sum = 0.0f;
    #pragma unroll
    for (int am = 0; am < 2; am++) {
        #pragma unroll
        for (int bn = 0; bn < 8; bn++) {
            #pragma unroll
            for (int k = 0; k < 4; k++) {
                float e = __expf(0.5f * d[am][bn][k]);
                if (maskt) {
                    int row = rbase + am * 16 + ((k >> 1) << 3);
                    int col = cbase + bn * 8 + (k & 1);
                    if (col < row) e = 0.0f;
                }
                sum += e;
            }
        }
    }

    #pragma unroll
    for (int o = 16; o > 0; o >>= 1)
        sum += __shfl_xor_sync(0xFFFFFFFFu, sum, o);

    __shared__ float wsum[8];
    if (lane == 0) wsum[wid] = sum;
    __syncthreads();
    if (tid == 0) {
        float s = 0.0f;
        #pragma unroll
        for (int i = 0; i < 8; i++) s += wsum[i];
        atomicAdd(&g_main, (double)s);
    }
}

// ---------------------------------------------------------------------------
__global__ void fin_k(float* __restrict__ out) {
    double sim_all = g_main + g_sims;
    out[0] = (float)(log(sim_all) - log(g_sims));
}

extern "C" void kernel_launch(void* const* d_in, const int* in_sizes, int n_in,
                              void* d_out, int out_size) {
    const float* x = (const float*)d_in[0];
    float* out = (float*)d_out;

    cudaFuncSetAttribute(tile_k, cudaFuncAttributeMaxDynamicSharedMemorySize, SMEM_TOTAL);

    init_k<<<1, 1>>>();
    normalize_k<<<NROWS, 256>>>(x);
    diag_k<<<NHALF, 256>>>(x);
    tile_k<<<1024 + 2 * 528, 256, SMEM_TOTAL>>>();
    fin_k<<<1, 1>>>(out);
}